// round 5
// baseline (speedup 1.0000x reference)
#include <cuda_runtime.h>
#include <cuda_bf16.h>

// NormalsRenderer: B=512, N=512.
// out[b] = normalize( sum_i acc_i * n_i ),  acc_i = sum_{j!=i} exp(-acos(clip(<n_i,n_j>)))
// Identities (uniform positive scales cancel under the final normalize):
//   - division by max(new_weights) dropped; exp(-acos d) = const * exp(asin d)
//   - u = sat(1-|d|);  asin(|d|)*log2e = LHPI + sqrt(u)*Q(u)  (cubic Q)
//   - w = exp2( copysign( LHPI + sqrt(u)*Q(u), d ) )
// Symmetry w_ij = w_ji via cyclic offsets (each unordered pair once): thread t owns
// rows (t, t+256); offset o pairs (t, t+o) and (t+256, (t+o)^256); local accumulate +
// smem "gift" to partner rows. Offsets split across 2 CTAs/batch (grid=1024); the
// second-finishing CTA of each batch fuses the combine+normalize (atomic counter).
// j-side normals held in smem as packed bf16x2 words to halve crossbar traffic
// (the measured binding resource); i-side and gifts remain f32.

#define NPTS 512
#define TPB  256
#define GPH  4

typedef unsigned long long ull;
typedef unsigned int uint;

// -log2(e) * p_AS(1-u) re-expanded in u, and log2(e)*pi/2
#define Q0f (-2.0401824f)
#define Q1f (-0.17280645f)
#define Q2f (-0.026074023f)
#define Q3f (-0.027020667f)
#define LHPIf (2.2661800709f)

__device__ float g_stage[1024][3];   // per-CTA partial weighted sums
__device__ int   g_cnt[512];         // per-batch arrival counters (left at 0)

__device__ __forceinline__ ull pack2(float lo, float hi) {
    ull r; asm("mov.b64 %0, {%1, %2};" : "=l"(r) : "f"(lo), "f"(hi)); return r;
}
__device__ __forceinline__ void unpack2(ull v, float& lo, float& hi) {
    asm("mov.b64 {%0, %1}, %2;" : "=f"(lo), "=f"(hi) : "l"(v));
}
__device__ __forceinline__ ull fma2(ull a, ull b, ull c) {
    ull d; asm("fma.rn.f32x2 %0, %1, %2, %3;" : "=l"(d) : "l"(a), "l"(b), "l"(c)); return d;
}
__device__ __forceinline__ ull mul2(ull a, ull b) {
    ull d; asm("mul.rn.f32x2 %0, %1, %2;" : "=l"(d) : "l"(a), "l"(b)); return d;
}
__device__ __forceinline__ ull add2(ull a, ull b) {
    ull d; asm("add.rn.f32x2 %0, %1, %2;" : "=l"(d) : "l"(a), "l"(b)); return d;
}
__device__ __forceinline__ float sqrta(float x) {
    float r; asm("sqrt.approx.f32 %0, %1;" : "=f"(r) : "f"(x)); return r;
}
__device__ __forceinline__ float ex2a(float x) {
    float r; asm("ex2.approx.f32 %0, %1;" : "=f"(r) : "f"(x)); return r;
}
__device__ __forceinline__ uint bf16bits(float v) {
    return (uint)__bfloat16_as_ushort(__float2bfloat16(v));   // round-to-nearest
}

__global__ __launch_bounds__(TPB, 8)
void normals_pair_kernel(const float* __restrict__ normals,
                         float* __restrict__ out)
{
    // sw*[k] word: low16 = bf16(v_k), high16 = bf16(v_{k^256})
    __shared__ uint  swx[NPTS], swy[NPTS], swz[NPTS];       // 6 KB
    __shared__ float gift[2][GPH][NPTS];                    // 16 KB double-buffered
    __shared__ float sred[3][TPB / 32];

    const int b    = blockIdx.x >> 1;
    const int half = blockIdx.x & 1;
    const int t    = threadIdx.x;

    const float* base = normals + (size_t)b * NPTS * 3;
    {
        float x0 = base[t * 3 + 0],         y0 = base[t * 3 + 1],         z0 = base[t * 3 + 2];
        float x1 = base[(t + 256) * 3 + 0], y1 = base[(t + 256) * 3 + 1], z1 = base[(t + 256) * 3 + 2];
        uint hx0 = bf16bits(x0), hy0 = bf16bits(y0), hz0 = bf16bits(z0);
        uint hx1 = bf16bits(x1), hy1 = bf16bits(y1), hz1 = bf16bits(z1);
        swx[t] = hx0 | (hx1 << 16);  swx[t + 256] = hx1 | (hx0 << 16);
        swy[t] = hy0 | (hy1 << 16);  swy[t + 256] = hy1 | (hy0 << 16);
        swz[t] = hz0 | (hz1 << 16);  swz[t + 256] = hz1 | (hz0 << 16);
    }
    __syncthreads();

    // i-side operands stay full f32 (loaded fresh; packed (row t, row t+256))
    const ull xi2 = pack2(base[t * 3 + 0], base[(t + 256) * 3 + 0]);
    const ull yi2 = pack2(base[t * 3 + 1], base[(t + 256) * 3 + 1]);
    const ull zi2 = pack2(base[t * 3 + 2], base[(t + 256) * 3 + 2]);

    const ull q3v = pack2(Q3f, Q3f), q2v = pack2(Q2f, Q2f);
    const ull q1v = pack2(Q1f, Q1f), q0v = pack2(Q0f, Q0f);
    const ull lh2 = pack2(LHPIf, LHPIf);

    ull accA = pack2(0.0f, 0.0f);
    ull accB = pack2(0.0f, 0.0f);

    // DO_GIFT=0 only for o=256 (self-partner pair: local accumulation is exact).
    #define PAIR_COMPUTE(K, GI, BUF, ACC, DO_GIFT)                                     \
    {                                                                                  \
        const int k_ = (K);                                                            \
        const uint wx = swx[k_], wy = swy[k_], wz = swz[k_];                           \
        ull njx = pack2(__uint_as_float(wx << 16), __uint_as_float(wx & 0xFFFF0000u)); \
        ull njy = pack2(__uint_as_float(wy << 16), __uint_as_float(wy & 0xFFFF0000u)); \
        ull njz = pack2(__uint_as_float(wz << 16), __uint_as_float(wz & 0xFFFF0000u)); \
        ull d2 = fma2(zi2, njz, fma2(yi2, njy, mul2(xi2, njx)));                       \
        float da, db; unpack2(d2, da, db);                                             \
        float ua = __saturatef(1.0f - fabsf(da));                                      \
        float ub = __saturatef(1.0f - fabsf(db));                                      \
        float sa = sqrta(ua), sb = sqrta(ub);                                          \
        ull u2 = pack2(ua, ub);                                                        \
        ull p2 = fma2(u2, q3v, q2v);                                                   \
        p2 = fma2(u2, p2, q1v);                                                        \
        p2 = fma2(u2, p2, q0v);                                                        \
        ull g2 = fma2(pack2(sa, sb), p2, lh2);                                         \
        float ga, gb; unpack2(g2, ga, gb);                                             \
        uint ea = __float_as_uint(ga) | (__float_as_uint(da) & 0x80000000u);           \
        uint eb = __float_as_uint(gb) | (__float_as_uint(db) & 0x80000000u);           \
        float wa = ex2a(__uint_as_float(ea));                                          \
        float wb = ex2a(__uint_as_float(eb));                                          \
        ACC = add2(ACC, pack2(wa, wb));                                                \
        if (DO_GIFT) {                                                                 \
            gift[BUF][GI][k_]       = wa;                                              \
            gift[BUF][GI][k_ ^ 256] = wb;                                              \
        }                                                                              \
    }

    int k   = t + (half ? 129 : 1);
    int buf = 0;
    const int NP = half ? 31 : 32;

    #pragma unroll 1
    for (int p = 0; p < NP; ++p) {
        PAIR_COMPUTE(k + 0, 0, buf, accA, 1);
        PAIR_COMPUTE(k + 1, 1, buf, accB, 1);
        PAIR_COMPUTE(k + 2, 2, buf, accA, 1);
        PAIR_COMPUTE(k + 3, 3, buf, accB, 1);
        __syncthreads();
        accA = add2(accA, pack2(gift[buf][0][t], gift[buf][0][t + 256]));
        accB = add2(accB, pack2(gift[buf][1][t], gift[buf][1][t + 256]));
        accA = add2(accA, pack2(gift[buf][2][t], gift[buf][2][t + 256]));
        accB = add2(accB, pack2(gift[buf][3][t], gift[buf][3][t + 256]));
        buf ^= 1;
        k += GPH;
    }

    if (half) {   // tail: o = 253, 254, 255 gifted; o = 256 ungifted
        PAIR_COMPUTE(k + 0, 0, buf, accA, 1);
        PAIR_COMPUTE(k + 1, 1, buf, accB, 1);
        PAIR_COMPUTE(k + 2, 2, buf, accA, 1);
        PAIR_COMPUTE(k + 3, 3, buf, accB, 0);
        __syncthreads();
        accA = add2(accA, pack2(gift[buf][0][t], gift[buf][0][t + 256]));
        accB = add2(accB, pack2(gift[buf][1][t], gift[buf][1][t + 256]));
        accA = add2(accA, pack2(gift[buf][2][t], gift[buf][2][t + 256]));
    }

    ull acc2 = add2(accA, accB);
    float w0, w1; unpack2(acc2, w0, w1);

    // Weighted contribution: reload exact f32 normals (L2-hot) for the epilogue.
    const float ex0 = base[t * 3 + 0],         ey0 = base[t * 3 + 1],         ez0 = base[t * 3 + 2];
    const float ex1 = base[(t + 256) * 3 + 0], ey1 = base[(t + 256) * 3 + 1], ez1 = base[(t + 256) * 3 + 2];
    float vx = fmaf(w1, ex1, w0 * ex0);
    float vy = fmaf(w1, ey1, w0 * ey0);
    float vz = fmaf(w1, ez1, w0 * ez0);

    #pragma unroll
    for (int s = 16; s >= 1; s >>= 1) {
        vx += __shfl_down_sync(0xffffffffu, vx, s);
        vy += __shfl_down_sync(0xffffffffu, vy, s);
        vz += __shfl_down_sync(0xffffffffu, vz, s);
    }
    const int lane = t & 31, warp = t >> 5;
    if (lane == 0) { sred[0][warp] = vx; sred[1][warp] = vy; sred[2][warp] = vz; }
    __syncthreads();

    if (t == 0) {
        float rx = 0.0f, ry = 0.0f, rz = 0.0f;
        #pragma unroll
        for (int wI = 0; wI < TPB / 32; ++wI) {
            rx += sred[0][wI]; ry += sred[1][wI]; rz += sred[2][wI];
        }
        g_stage[blockIdx.x][0] = rx;
        g_stage[blockIdx.x][1] = ry;
        g_stage[blockIdx.x][2] = rz;
        __threadfence();
        int old = atomicAdd(&g_cnt[b], 1);
        if (old == 1) {   // second arrival: combine + normalize + write, reset counter
            __threadfence();
            const int other = blockIdx.x ^ 1;
            rx += g_stage[other][0];
            ry += g_stage[other][1];
            rz += g_stage[other][2];
            float ss  = fmaf(rx, rx, fmaf(ry, ry, rz * rz));
            float inv = rsqrtf(fmaxf(ss, 1e-20f));
            out[b * 3 + 0] = rx * inv;
            out[b * 3 + 1] = ry * inv;
            out[b * 3 + 2] = rz * inv;
            g_cnt[b] = 0;   // deterministic state for graph replay
        }
    }
}

extern "C" void kernel_launch(void* const* d_in, const int* in_sizes, int n_in,
                              void* d_out, int out_size)
{
    const float* normals = (const float*)d_in[0];  // [512, 512, 3] f32
    // d_in[1] = weights: unused by the reference math.
    float* out = (float*)d_out;                    // [512, 3] f32

    normals_pair_kernel<<<1024, TPB>>>(normals, out);
}

// round 6
// speedup vs baseline: 1.0390x; 1.0390x over previous
#include <cuda_runtime.h>
#include <cuda_bf16.h>

// NormalsRenderer: B=512, N=512.
// out[b] = normalize( sum_i acc_i * n_i ),  acc_i = sum_{j!=i} exp(-acos(clip(<n_i,n_j>)))
// Identities (uniform positive scales cancel under the final normalize):
//   - division by max(new_weights) dropped; exp(-acos d) = const * exp(asin d)
//   - u = sat(1-|d|);  asin(|d|)*log2e = LHPI + sqrt(u)*Q(u)  (cubic Q)
//   - w = exp2( copysign( LHPI + sqrt(u)*Q(u), d ) )
// Symmetry w_ij = w_ji via cyclic offsets (each unordered pair once): thread t owns
// rows (t, t+256); offset o pairs (t, t+o) and (t+256, (t+o)^256); local accumulate +
// smem "gift" to partner rows, double-buffered, 1 sync per 4 offsets. Offsets split
// across 2 CTAs/batch (grid=1024); second-finishing CTA combines + normalizes.
// j-side smem is full f32 (bf16 compression regressed: it traded cheap LSU bytes for
// alu-pipe unpacks, and alu issue slots are the binding resource).

#define NPTS 512
#define TPB  256
#define GPH  4

typedef unsigned long long ull;
typedef unsigned int uint;

// -log2(e) * p_AS(1-u) re-expanded in u, and log2(e)*pi/2
#define Q0f (-2.0401824f)
#define Q1f (-0.17280645f)
#define Q2f (-0.026074023f)
#define Q3f (-0.027020667f)
#define LHPIf (2.2661800709f)

__device__ float g_stage[1024][3];   // per-CTA partial weighted sums
__device__ int   g_cnt[512];         // per-batch arrival counters (reset to 0 each use)

__device__ __forceinline__ ull pack2(float lo, float hi) {
    ull r; asm("mov.b64 %0, {%1, %2};" : "=l"(r) : "f"(lo), "f"(hi)); return r;
}
__device__ __forceinline__ void unpack2(ull v, float& lo, float& hi) {
    asm("mov.b64 {%0, %1}, %2;" : "=f"(lo), "=f"(hi) : "l"(v));
}
__device__ __forceinline__ ull fma2(ull a, ull b, ull c) {
    ull d; asm("fma.rn.f32x2 %0, %1, %2, %3;" : "=l"(d) : "l"(a), "l"(b), "l"(c)); return d;
}
__device__ __forceinline__ ull mul2(ull a, ull b) {
    ull d; asm("mul.rn.f32x2 %0, %1, %2;" : "=l"(d) : "l"(a), "l"(b)); return d;
}
__device__ __forceinline__ ull add2(ull a, ull b) {
    ull d; asm("add.rn.f32x2 %0, %1, %2;" : "=l"(d) : "l"(a), "l"(b)); return d;
}
__device__ __forceinline__ float sqrta(float x) {
    float r; asm("sqrt.approx.f32 %0, %1;" : "=f"(r) : "f"(x)); return r;
}
__device__ __forceinline__ float ex2a(float x) {
    float r; asm("ex2.approx.f32 %0, %1;" : "=f"(r) : "f"(x)); return r;
}

__global__ __launch_bounds__(TPB, 7)
void normals_pair_kernel(const float* __restrict__ normals,
                         float* __restrict__ out)
{
    // sw*[k] = (v_k, v_{k^256}): one LDS.64 yields the packed j-operand for both rows.
    __shared__ float2 swx[NPTS], swy[NPTS], swz[NPTS];     // 12 KB
    __shared__ float  gift[2][GPH][NPTS];                  // 16 KB double-buffered
    __shared__ float  sred[3][TPB / 32];

    const int b    = blockIdx.x >> 1;
    const int half = blockIdx.x & 1;
    const int t    = threadIdx.x;

    const float* base = normals + (size_t)b * NPTS * 3;
    {
        float x0 = base[t * 3 + 0],         y0 = base[t * 3 + 1],         z0 = base[t * 3 + 2];
        float x1 = base[(t + 256) * 3 + 0], y1 = base[(t + 256) * 3 + 1], z1 = base[(t + 256) * 3 + 2];
        swx[t] = make_float2(x0, x1);  swx[t + 256] = make_float2(x1, x0);
        swy[t] = make_float2(y0, y1);  swy[t + 256] = make_float2(y1, y0);
        swz[t] = make_float2(z0, z1);  swz[t + 256] = make_float2(z1, z0);
    }
    __syncthreads();

    // i-side packed operands (row t, row t+256)
    const ull xi2 = pack2(base[t * 3 + 0], base[(t + 256) * 3 + 0]);
    const ull yi2 = pack2(base[t * 3 + 1], base[(t + 256) * 3 + 1]);
    const ull zi2 = pack2(base[t * 3 + 2], base[(t + 256) * 3 + 2]);

    const ull q3v = pack2(Q3f, Q3f), q2v = pack2(Q2f, Q2f);
    const ull q1v = pack2(Q1f, Q1f), q0v = pack2(Q0f, Q0f);
    const ull lh2 = pack2(LHPIf, LHPIf);

    ull accA = pack2(0.0f, 0.0f);
    ull accB = pack2(0.0f, 0.0f);

    const ull* __restrict__ px = (const ull*)swx;
    const ull* __restrict__ py = (const ull*)swy;
    const ull* __restrict__ pz = (const ull*)swz;

    // DO_GIFT=0 only for o=256 (self-partner pair: local accumulation is exact).
    #define PAIR_COMPUTE(K, GI, BUF, ACC, DO_GIFT)                                     \
    {                                                                                  \
        const int k_ = (K);                                                            \
        const ull njx = px[k_], njy = py[k_], njz = pz[k_];                            \
        ull d2 = fma2(zi2, njz, fma2(yi2, njy, mul2(xi2, njx)));                       \
        float da, db; unpack2(d2, da, db);                                             \
        float ua = __saturatef(1.0f - fabsf(da));                                      \
        float ub = __saturatef(1.0f - fabsf(db));                                      \
        float sa = sqrta(ua), sb = sqrta(ub);                                          \
        ull u2 = pack2(ua, ub);                                                        \
        ull p2 = fma2(u2, q3v, q2v);                                                   \
        p2 = fma2(u2, p2, q1v);                                                        \
        p2 = fma2(u2, p2, q0v);                                                        \
        ull g2 = fma2(pack2(sa, sb), p2, lh2);                                         \
        float ga, gb; unpack2(g2, ga, gb);                                             \
        uint ea = __float_as_uint(ga) | (__float_as_uint(da) & 0x80000000u);           \
        uint eb = __float_as_uint(gb) | (__float_as_uint(db) & 0x80000000u);           \
        float wa = ex2a(__uint_as_float(ea));                                          \
        float wb = ex2a(__uint_as_float(eb));                                          \
        ACC = add2(ACC, pack2(wa, wb));                                                \
        if (DO_GIFT) {                                                                 \
            float* gp = &gift[BUF][GI][0];                                             \
            gp[k_] = wa;                                                               \
            *(float*)((char*)(gp + k_) + ((k_ < 256) ? 1024 : -1024)) = wb;            \
        }                                                                              \
    }

    int k   = t + (half ? 129 : 1);
    int buf = 0;
    const int NP = half ? 31 : 32;

    #pragma unroll 1
    for (int p = 0; p < NP; ++p) {
        PAIR_COMPUTE(k + 0, 0, buf, accA, 1);
        PAIR_COMPUTE(k + 1, 1, buf, accB, 1);
        PAIR_COMPUTE(k + 2, 2, buf, accA, 1);
        PAIR_COMPUTE(k + 3, 3, buf, accB, 1);
        __syncthreads();
        accA = add2(accA, pack2(gift[buf][0][t], gift[buf][0][t + 256]));
        accB = add2(accB, pack2(gift[buf][1][t], gift[buf][1][t + 256]));
        accA = add2(accA, pack2(gift[buf][2][t], gift[buf][2][t + 256]));
        accB = add2(accB, pack2(gift[buf][3][t], gift[buf][3][t + 256]));
        buf ^= 1;
        k += GPH;
    }

    if (half) {   // tail: o = 253, 254, 255 gifted; o = 256 ungifted
        PAIR_COMPUTE(k + 0, 0, buf, accA, 1);
        PAIR_COMPUTE(k + 1, 1, buf, accB, 1);
        PAIR_COMPUTE(k + 2, 2, buf, accA, 1);
        PAIR_COMPUTE(k + 3, 3, buf, accB, 0);
        __syncthreads();
        accA = add2(accA, pack2(gift[buf][0][t], gift[buf][0][t + 256]));
        accB = add2(accB, pack2(gift[buf][1][t], gift[buf][1][t + 256]));
        accA = add2(accA, pack2(gift[buf][2][t], gift[buf][2][t + 256]));
    }

    ull acc2 = add2(accA, accB);
    float w0, w1; unpack2(acc2, w0, w1);

    // Weighted contribution: reload exact f32 normals (L2-hot) to keep live regs low.
    const float ex0 = base[t * 3 + 0],         ey0 = base[t * 3 + 1],         ez0 = base[t * 3 + 2];
    const float ex1 = base[(t + 256) * 3 + 0], ey1 = base[(t + 256) * 3 + 1], ez1 = base[(t + 256) * 3 + 2];
    float vx = fmaf(w1, ex1, w0 * ex0);
    float vy = fmaf(w1, ey1, w0 * ey0);
    float vz = fmaf(w1, ez1, w0 * ez0);

    #pragma unroll
    for (int s = 16; s >= 1; s >>= 1) {
        vx += __shfl_down_sync(0xffffffffu, vx, s);
        vy += __shfl_down_sync(0xffffffffu, vy, s);
        vz += __shfl_down_sync(0xffffffffu, vz, s);
    }
    const int lane = t & 31, warp = t >> 5;
    if (lane == 0) { sred[0][warp] = vx; sred[1][warp] = vy; sred[2][warp] = vz; }
    __syncthreads();

    if (t == 0) {
        float rx = 0.0f, ry = 0.0f, rz = 0.0f;
        #pragma unroll
        for (int wI = 0; wI < TPB / 32; ++wI) {
            rx += sred[0][wI]; ry += sred[1][wI]; rz += sred[2][wI];
        }
        g_stage[blockIdx.x][0] = rx;
        g_stage[blockIdx.x][1] = ry;
        g_stage[blockIdx.x][2] = rz;
        __threadfence();
        int old = atomicAdd(&g_cnt[b], 1);
        if (old == 1) {   // second arrival: combine + normalize + write, reset counter
            __threadfence();
            const int other = blockIdx.x ^ 1;
            rx += g_stage[other][0];
            ry += g_stage[other][1];
            rz += g_stage[other][2];
            float ss  = fmaf(rx, rx, fmaf(ry, ry, rz * rz));
            float inv = rsqrtf(fmaxf(ss, 1e-20f));
            out[b * 3 + 0] = rx * inv;
            out[b * 3 + 1] = ry * inv;
            out[b * 3 + 2] = rz * inv;
            g_cnt[b] = 0;   // deterministic state for graph replay
        }
    }
}

extern "C" void kernel_launch(void* const* d_in, const int* in_sizes, int n_in,
                              void* d_out, int out_size)
{
    const float* normals = (const float*)d_in[0];  // [512, 512, 3] f32
    // d_in[1] = weights: unused by the reference math.
    float* out = (float*)d_out;                    // [512, 3] f32

    normals_pair_kernel<<<1024, TPB>>>(normals, out);
}

// round 7
// speedup vs baseline: 1.0752x; 1.0348x over previous
#include <cuda_runtime.h>
#include <cuda_bf16.h>

// NormalsRenderer: B=512, N=512.
// out[b] = normalize( sum_i acc_i * n_i ),  acc_i = sum_{j!=i} exp(-acos(clip(<n_i,n_j>)))
// Identities (uniform positive scales cancel under the final normalize):
//   - division by max(new_weights) dropped; exp(-acos d) = const * exp(asin d)
//   - u = sat(1-|d|);  asin(|d|)*log2e = LHPI + sqrt(u)*Q(u)  (cubic Q)
//   - w = exp2( copysign( LHPI + sqrt(u)*Q(u), d ) )
// Symmetry w_ij = w_ji via cyclic offsets (each unordered pair once): thread t owns
// rows (t, t+256); offset o pairs (t, t+o) and (t+256, (t+o)^256); local accumulate +
// packed float2 smem "gift" to the partner thread, double-buffered, 1 sync / 4 offsets.
// Offsets split across 2 CTAs/batch (grid=1024); second finisher combines+normalizes.
// LSU diet: j-operands as float4(x,x',y,y')+float2(z,z') (2 issues), gift as one
// STS.64/LDS.64 pair — 4 LSU issues per body total.

#define NPTS 512
#define TPB  256
#define GPH  4

typedef unsigned long long ull;
typedef unsigned int uint;

// -log2(e) * p_AS(1-u) re-expanded in u, and log2(e)*pi/2
#define Q0f (-2.0401824f)
#define Q1f (-0.17280645f)
#define Q2f (-0.026074023f)
#define Q3f (-0.027020667f)
#define LHPIf (2.2661800709f)

__device__ float g_stage[1024][3];   // per-CTA partial weighted sums
__device__ int   g_cnt[512];         // per-batch arrival counters (reset to 0 each use)

__device__ __forceinline__ ull pack2(float lo, float hi) {
    ull r; asm("mov.b64 %0, {%1, %2};" : "=l"(r) : "f"(lo), "f"(hi)); return r;
}
__device__ __forceinline__ void unpack2(ull v, float& lo, float& hi) {
    asm("mov.b64 {%0, %1}, %2;" : "=f"(lo), "=f"(hi) : "l"(v));
}
__device__ __forceinline__ ull fma2(ull a, ull b, ull c) {
    ull d; asm("fma.rn.f32x2 %0, %1, %2, %3;" : "=l"(d) : "l"(a), "l"(b), "l"(c)); return d;
}
__device__ __forceinline__ ull mul2(ull a, ull b) {
    ull d; asm("mul.rn.f32x2 %0, %1, %2;" : "=l"(d) : "l"(a), "l"(b)); return d;
}
__device__ __forceinline__ ull add2(ull a, ull b) {
    ull d; asm("add.rn.f32x2 %0, %1, %2;" : "=l"(d) : "l"(a), "l"(b)); return d;
}
__device__ __forceinline__ float sqrta(float x) {
    float r; asm("sqrt.approx.f32 %0, %1;" : "=f"(r) : "f"(x)); return r;
}
__device__ __forceinline__ float ex2a(float x) {
    float r; asm("ex2.approx.f32 %0, %1;" : "=f"(r) : "f"(x)); return r;
}

__global__ __launch_bounds__(TPB, 7)
void normals_pair_kernel(const float* __restrict__ normals,
                         float* __restrict__ out)
{
    // swxy[k] = (x_k, x_{k^256}, y_k, y_{k^256}); swz[k] = (z_k, z_{k^256}).
    __shared__ float4 swxy[NPTS];                          // 8 KB
    __shared__ float2 swz[NPTS];                           // 4 KB
    __shared__ float2 gift[2][GPH][TPB];                   // 16 KB double-buffered
    __shared__ float  sred[3][TPB / 32];

    const int b    = blockIdx.x >> 1;
    const int half = blockIdx.x & 1;
    const int t    = threadIdx.x;

    const float* base = normals + (size_t)b * NPTS * 3;
    {
        float x0 = base[t * 3 + 0],         y0 = base[t * 3 + 1],         z0 = base[t * 3 + 2];
        float x1 = base[(t + 256) * 3 + 0], y1 = base[(t + 256) * 3 + 1], z1 = base[(t + 256) * 3 + 2];
        swxy[t]       = make_float4(x0, x1, y0, y1);
        swxy[t + 256] = make_float4(x1, x0, y1, y0);
        swz[t]        = make_float2(z0, z1);
        swz[t + 256]  = make_float2(z1, z0);
    }
    __syncthreads();

    // i-side packed operands (row t, row t+256)
    const ull xi2 = pack2(base[t * 3 + 0], base[(t + 256) * 3 + 0]);
    const ull yi2 = pack2(base[t * 3 + 1], base[(t + 256) * 3 + 1]);
    const ull zi2 = pack2(base[t * 3 + 2], base[(t + 256) * 3 + 2]);

    const ull q3v = pack2(Q3f, Q3f), q2v = pack2(Q2f, Q2f);
    const ull q1v = pack2(Q1f, Q1f), q0v = pack2(Q0f, Q0f);
    const ull lh2 = pack2(LHPIf, LHPIf);

    ull accA = pack2(0.0f, 0.0f);
    ull accB = pack2(0.0f, 0.0f);

    // DO_GIFT=0 only for o=256 (self-partner pair: local accumulation is exact).
    #define PAIR_COMPUTE(K, GI, BUF, ACC, DO_GIFT)                                     \
    {                                                                                  \
        const int k_ = (K);                                                            \
        const float4 jxy = swxy[k_];          /* LDS.128 */                            \
        const float2 jz  = swz[k_];           /* LDS.64  */                            \
        ull njx = pack2(jxy.x, jxy.y);                                                 \
        ull njy = pack2(jxy.z, jxy.w);                                                 \
        ull njz = pack2(jz.x, jz.y);                                                   \
        ull d2 = fma2(zi2, njz, fma2(yi2, njy, mul2(xi2, njx)));                       \
        float da, db; unpack2(d2, da, db);                                             \
        float ua = __saturatef(1.0f - fabsf(da));                                      \
        float ub = __saturatef(1.0f - fabsf(db));                                      \
        float sa = sqrta(ua), sb = sqrta(ub);                                          \
        ull u2 = pack2(ua, ub);                                                        \
        ull p2 = fma2(u2, q3v, q2v);                                                   \
        p2 = fma2(u2, p2, q1v);                                                        \
        p2 = fma2(u2, p2, q0v);                                                        \
        ull g2 = fma2(pack2(sa, sb), p2, lh2);                                         \
        float ga, gb; unpack2(g2, ga, gb);                                             \
        uint ea = __float_as_uint(ga) | (__float_as_uint(da) & 0x80000000u);           \
        uint eb = __float_as_uint(gb) | (__float_as_uint(db) & 0x80000000u);           \
        float wa = ex2a(__uint_as_float(ea));                                          \
        float wb = ex2a(__uint_as_float(eb));                                          \
        ACC = add2(ACC, pack2(wa, wb));                                                \
        if (DO_GIFT) {                                                                 \
            const bool lo_ = k_ < 256;                                                 \
            float2 gv;                                                                 \
            gv.x = lo_ ? wa : wb;                                                      \
            gv.y = lo_ ? wb : wa;                                                      \
            gift[BUF][GI][k_ & 255] = gv;     /* STS.64 */                             \
        }                                                                              \
    }

    int k   = t + (half ? 129 : 1);
    int buf = 0;
    const int NP = half ? 31 : 32;

    #pragma unroll 1
    for (int p = 0; p < NP; ++p) {
        PAIR_COMPUTE(k + 0, 0, buf, accA, 1);
        PAIR_COMPUTE(k + 1, 1, buf, accB, 1);
        PAIR_COMPUTE(k + 2, 2, buf, accA, 1);
        PAIR_COMPUTE(k + 3, 3, buf, accB, 1);
        __syncthreads();
        {
            float2 r0 = gift[buf][0][t];
            float2 r1 = gift[buf][1][t];
            float2 r2 = gift[buf][2][t];
            float2 r3 = gift[buf][3][t];
            accA = add2(accA, pack2(r0.x, r0.y));
            accB = add2(accB, pack2(r1.x, r1.y));
            accA = add2(accA, pack2(r2.x, r2.y));
            accB = add2(accB, pack2(r3.x, r3.y));
        }
        buf ^= 1;
        k += GPH;
    }

    if (half) {   // tail: o = 253, 254, 255 gifted; o = 256 ungifted
        PAIR_COMPUTE(k + 0, 0, buf, accA, 1);
        PAIR_COMPUTE(k + 1, 1, buf, accB, 1);
        PAIR_COMPUTE(k + 2, 2, buf, accA, 1);
        PAIR_COMPUTE(k + 3, 3, buf, accB, 0);
        __syncthreads();
        {
            float2 r0 = gift[buf][0][t];
            float2 r1 = gift[buf][1][t];
            float2 r2 = gift[buf][2][t];
            accA = add2(accA, pack2(r0.x, r0.y));
            accB = add2(accB, pack2(r1.x, r1.y));
            accA = add2(accA, pack2(r2.x, r2.y));
        }
    }

    ull acc2 = add2(accA, accB);
    float w0, w1; unpack2(acc2, w0, w1);

    // Weighted contribution: reload exact f32 normals (L2-hot) to keep live regs low.
    const float ex0 = base[t * 3 + 0],         ey0 = base[t * 3 + 1],         ez0 = base[t * 3 + 2];
    const float ex1 = base[(t + 256) * 3 + 0], ey1 = base[(t + 256) * 3 + 1], ez1 = base[(t + 256) * 3 + 2];
    float vx = fmaf(w1, ex1, w0 * ex0);
    float vy = fmaf(w1, ey1, w0 * ey0);
    float vz = fmaf(w1, ez1, w0 * ez0);

    #pragma unroll
    for (int s = 16; s >= 1; s >>= 1) {
        vx += __shfl_down_sync(0xffffffffu, vx, s);
        vy += __shfl_down_sync(0xffffffffu, vy, s);
        vz += __shfl_down_sync(0xffffffffu, vz, s);
    }
    const int lane = t & 31, warp = t >> 5;
    if (lane == 0) { sred[0][warp] = vx; sred[1][warp] = vy; sred[2][warp] = vz; }
    __syncthreads();

    if (t == 0) {
        float rx = 0.0f, ry = 0.0f, rz = 0.0f;
        #pragma unroll
        for (int wI = 0; wI < TPB / 32; ++wI) {
            rx += sred[0][wI]; ry += sred[1][wI]; rz += sred[2][wI];
        }
        g_stage[blockIdx.x][0] = rx;
        g_stage[blockIdx.x][1] = ry;
        g_stage[blockIdx.x][2] = rz;
        __threadfence();
        int old = atomicAdd(&g_cnt[b], 1);
        if (old == 1) {   // second arrival: combine + normalize + write, reset counter
            __threadfence();
            const int other = blockIdx.x ^ 1;
            rx += g_stage[other][0];
            ry += g_stage[other][1];
            rz += g_stage[other][2];
            float ss  = fmaf(rx, rx, fmaf(ry, ry, rz * rz));
            float inv = rsqrtf(fmaxf(ss, 1e-20f));
            out[b * 3 + 0] = rx * inv;
            out[b * 3 + 1] = ry * inv;
            out[b * 3 + 2] = rz * inv;
            g_cnt[b] = 0;   // deterministic state for graph replay
        }
    }
}

extern "C" void kernel_launch(void* const* d_in, const int* in_sizes, int n_in,
                              void* d_out, int out_size)
{
    const float* normals = (const float*)d_in[0];  // [512, 512, 3] f32
    // d_in[1] = weights: unused by the reference math.
    float* out = (float*)d_out;                    // [512, 3] f32

    normals_pair_kernel<<<1024, TPB>>>(normals, out);
}